// round 16
// baseline (speedup 1.0000x reference)
#include <cuda_runtime.h>

// ThreeBodyAggregation — moment-factorized, fully fused, 1 row per block
// (R12 champion structure) + L1 prefetch of the tail's operands (w2/w1/
// biases) issued at kernel start so their load latency hides under the
// Phase A/B rbf stream.
//
// agg_l(b,i) = sum_{j,k} w_j w_k P_l(u_j.u_k) computed exactly via weighted
// direction moments (Legendre monomial expansion). All agg terms are weighted
// sums of SQUARES of the 20 moments:
//   agg0 = S^2
//   agg1 = |V|^2
//   agg2 = 1.5*||M||_F^2 - 0.5*S^2
//   agg3 = 2.5*||T||^2   - 1.5*|V|^2
// Then h = silu(agg @ w1^T + b1), o = h @ w2^T + b2, LayerNorm(o).

#define B_   4
#define N_   160
#define R_   64
#define EMB_ 128
#define HID_ 128
#define EPS_LN 1e-5f

__global__ __launch_bounds__(256, 5)
void tba_fused(const float* __restrict__ rbf,     // (B,N,N,R)
               const float* __restrict__ r_hat,   // (B,N,N,3)
               const float* __restrict__ mask,    // (B,N,N)
               const float* __restrict__ w_rad,   // (1,R)
               const float* __restrict__ b_rad,   // (1,)
               const float* __restrict__ w1,      // (HID,4)
               const float* __restrict__ b1,      // (HID,)
               const float* __restrict__ w2,      // (EMB,HID)
               const float* __restrict__ b2,      // (EMB,)
               const float* __restrict__ gamma,   // (EMB,)
               const float* __restrict__ beta,    // (EMB,)
               float* __restrict__ out)           // (B,N,EMB)
{
    __shared__ float s_w[N_];
    __shared__ float s_mask[N_];
    __shared__ float s_rh[N_ * 3];
    __shared__ float s_red[8][20];
    __shared__ float s_val[20];
    __shared__ float s_agg[4];
    __shared__ float s_h[HID_];
    __shared__ float s_o[EMB_];
    __shared__ float s_ln[4][2];

    const int tid  = threadIdx.x;
    const int lane = tid & 31;
    const int warp = tid >> 5;
    const int row  = blockIdx.x;
    const float brad = b_rad[0];

    // ---- Prefetch the tail's operands into L1 (zero register/SB cost).
    // GEMV reads w2 float4s at (warp*512 + 64*ee + lane) and +32, ee=0..7.
    {
        const float4* w2v = reinterpret_cast<const float4*>(w2);
        const float4* p = w2v + warp * 512 + lane;
        #pragma unroll
        for (int ee = 0; ee < 8; ++ee) {
            asm volatile("prefetch.global.L1 [%0];" :: "l"(p));
            asm volatile("prefetch.global.L1 [%0];" :: "l"(p + 32));
            p += 64;
        }
        if (tid < HID_) {
            asm volatile("prefetch.global.L1 [%0];"
                         :: "l"(reinterpret_cast<const float4*>(w1) + tid));
            asm volatile("prefetch.global.L1 [%0];" :: "l"(b1 + tid));
            asm volatile("prefetch.global.L1 [%0];" :: "l"(b2 + tid));
            asm volatile("prefetch.global.L1 [%0];" :: "l"(gamma + tid));
            asm volatile("prefetch.global.L1 [%0];" :: "l"(beta + tid));
        }
    }

    // ---- mask + r_hat rows (coalesced float4; needed in Phase B).
    if (tid < 40)
        reinterpret_cast<float4*>(s_mask)[tid] =
            reinterpret_cast<const float4*>(mask + (size_t)row * N_)[tid];
    if (tid < 120)
        reinterpret_cast<float4*>(s_rh)[tid] =
            reinterpret_cast<const float4*>(r_hat + (size_t)row * (N_ * 3))[tid];

    // 8 lanes per j-row; lane c owns w_rad float4s c and c+8.
    const int c = lane & 7;
    const float4* wr4 = reinterpret_cast<const float4*>(w_rad);
    const float4 wr0 = wr4[c];
    const float4 wr1 = wr4[c + 8];

    const float4* rbf4 =
        reinterpret_cast<const float4*>(rbf + (size_t)row * (N_ * R_));

    // ---- Phase A: warp w covers j = 20w..20w+19; 4 j-rows per pass
    // (lane>>3 picks the row), 5 passes in two half-batches (3 + 2 passes,
    // max 6 float4 live -> 48-reg fit).
    const int jb = warp * 20 + (lane >> 3);
    {
        float4 a0[3], a1[3];
        #pragma unroll
        for (int p = 0; p < 3; ++p) {
            const size_t base = (size_t)(jb + 4 * p) * (R_ / 4);
            a0[p] = rbf4[base + c];
            a1[p] = rbf4[base + c + 8];
        }
        #pragma unroll
        for (int p = 0; p < 3; ++p) {
            float v = a0[p].x * wr0.x;
            v = fmaf(a0[p].y, wr0.y, v);
            v = fmaf(a0[p].z, wr0.z, v);
            v = fmaf(a0[p].w, wr0.w, v);
            v = fmaf(a1[p].x, wr1.x, v);
            v = fmaf(a1[p].y, wr1.y, v);
            v = fmaf(a1[p].z, wr1.z, v);
            v = fmaf(a1[p].w, wr1.w, v);
            v += __shfl_xor_sync(0xffffffffu, v, 1);
            v += __shfl_xor_sync(0xffffffffu, v, 2);
            v += __shfl_xor_sync(0xffffffffu, v, 4);
            if (c == 0)
                s_w[jb + 4 * p] = __frcp_rn(1.f + __expf(-(v + brad)));
        }
    }
    {
        float4 a0[2], a1[2];
        #pragma unroll
        for (int p = 0; p < 2; ++p) {
            const size_t base = (size_t)(jb + 4 * (p + 3)) * (R_ / 4);
            a0[p] = rbf4[base + c];
            a1[p] = rbf4[base + c + 8];
        }
        #pragma unroll
        for (int p = 0; p < 2; ++p) {
            float v = a0[p].x * wr0.x;
            v = fmaf(a0[p].y, wr0.y, v);
            v = fmaf(a0[p].z, wr0.z, v);
            v = fmaf(a0[p].w, wr0.w, v);
            v = fmaf(a1[p].x, wr1.x, v);
            v = fmaf(a1[p].y, wr1.y, v);
            v = fmaf(a1[p].z, wr1.z, v);
            v = fmaf(a1[p].w, wr1.w, v);
            v += __shfl_xor_sync(0xffffffffu, v, 1);
            v += __shfl_xor_sync(0xffffffffu, v, 2);
            v += __shfl_xor_sync(0xffffffffu, v, 4);
            if (c == 0)
                s_w[jb + 4 * (p + 3)] = __frcp_rn(1.f + __expf(-(v + brad)));
        }
    }
    __syncthreads();

    // ---- Phase B: weighted direction moments (20 accumulators).
    float acc[20];
    #pragma unroll
    for (int q = 0; q < 20; ++q) acc[q] = 0.f;
    if (tid < N_) {
        const float w = s_w[tid] * s_mask[tid];
        const float x = s_rh[3 * tid];
        const float y = s_rh[3 * tid + 1];
        const float z = s_rh[3 * tid + 2];
        const float wx = w * x, wy = w * y, wz = w * z;
        const float wxx = wx * x, wyy = wy * y, wzz = wz * z;
        const float wxy = wx * y, wxz = wx * z, wyz = wy * z;
        acc[0]  = w;
        acc[1]  = wx;  acc[2]  = wy;  acc[3]  = wz;
        acc[4]  = wxx; acc[5]  = wyy; acc[6]  = wzz;
        acc[7]  = wxy; acc[8]  = wxz; acc[9]  = wyz;
        acc[10] = wxx * x; acc[11] = wyy * y; acc[12] = wzz * z;
        acc[13] = wxx * y; acc[14] = wxx * z;
        acc[15] = wyy * x; acc[16] = wyy * z;
        acc[17] = wzz * x; acc[18] = wzz * y;
        acc[19] = wxy * z;
    }
    // Packed 4-group reduce: 6 shuffles per 4 moments (30 total).
    #pragma unroll
    for (int g = 0; g < 5; ++g) {
        const int b = 4 * g;
        float keepA = (lane & 1) ? acc[b + 1] : acc[b + 0];
        float sendA = (lane & 1) ? acc[b + 0] : acc[b + 1];
        keepA += __shfl_xor_sync(0xffffffffu, sendA, 1);
        float keepB = (lane & 1) ? acc[b + 3] : acc[b + 2];
        float sendB = (lane & 1) ? acc[b + 2] : acc[b + 3];
        keepB += __shfl_xor_sync(0xffffffffu, sendB, 1);
        float keep = (lane & 2) ? keepB : keepA;
        float send = (lane & 2) ? keepA : keepB;
        keep += __shfl_xor_sync(0xffffffffu, send, 2);
        keep += __shfl_xor_sync(0xffffffffu, keep, 4);
        keep += __shfl_xor_sync(0xffffffffu, keep, 8);
        keep += __shfl_xor_sync(0xffffffffu, keep, 16);
        if (lane < 4) s_red[warp][b + lane] = keep;
    }
    __syncthreads();

    // ---- Combine: warp 0 lane q<20 sums 8 partials, squares with coef.
    if (warp == 0) {
        if (lane < 20) {
            float m = 0.f;
            #pragma unroll
            for (int u = 0; u < 8; ++u) m += s_red[u][lane];
            // coef: q0:1, q1-6:1, q7-9:2, q10-12:1, q13-18:3, q19:6
            float cf = 1.f;
            if (lane >= 7 && lane <= 9) cf = 2.f;
            else if (lane >= 13 && lane <= 18) cf = 3.f;
            else if (lane == 19) cf = 6.f;
            s_val[lane] = cf * m * m;
        }
        __syncwarp();
        if (lane == 0) {
            const float S2 = s_val[0];
            const float V2 = s_val[1] + s_val[2] + s_val[3];
            float Q2 = 0.f, Q3 = 0.f;
            #pragma unroll
            for (int q = 4; q < 10; ++q) Q2 += s_val[q];
            #pragma unroll
            for (int q = 10; q < 20; ++q) Q3 += s_val[q];
            s_agg[0] = S2;
            s_agg[1] = V2;
            s_agg[2] = 1.5f * Q2 - 0.5f * S2;
            s_agg[3] = 2.5f * Q3 - 1.5f * V2;
        }
    }
    __syncthreads();

    // ---- Phase C: h = silu(agg @ w1^T + b1). First 128 threads.
    if (tid < HID_) {
        const float4 wv1 = reinterpret_cast<const float4*>(w1)[tid];
        float hv = fmaf(s_agg[0], wv1.x,
                   fmaf(s_agg[1], wv1.y,
                   fmaf(s_agg[2], wv1.z,
                   fmaf(s_agg[3], wv1.w, b1[tid]))));
        hv = hv * __frcp_rn(1.f + __expf(-hv));
        s_h[tid] = hv;
    }
    __syncthreads();

    // Per-lane h slice in registers.
    const float4 hv = reinterpret_cast<const float4*>(s_h)[lane];

    // ---- GEMV: warp w handles outputs e = 16w..16w+15, paired (even lanes
    // carry e0 partials, odd e1): 5 shuffles per 2 outputs. w2 is L1-hot
    // from the prefetch issued at kernel start.
    const float4* w2v = reinterpret_cast<const float4*>(w2);
    #pragma unroll
    for (int ee = 0; ee < 8; ++ee) {
        const int e0 = warp * 16 + 2 * ee;
        const float4 wv0 = w2v[e0 * 32 + lane];
        const float4 wv1 = w2v[(e0 + 1) * 32 + lane];
        float acc0 = fmaf(wv0.x, hv.x, fmaf(wv0.y, hv.y,
                     fmaf(wv0.z, hv.z, wv0.w * hv.w)));
        float acc1 = fmaf(wv1.x, hv.x, fmaf(wv1.y, hv.y,
                     fmaf(wv1.z, hv.z, wv1.w * hv.w)));
        float keep = (lane & 1) ? acc1 : acc0;
        float send = (lane & 1) ? acc0 : acc1;
        keep += __shfl_xor_sync(0xffffffffu, send, 1);
        keep += __shfl_xor_sync(0xffffffffu, keep, 2);
        keep += __shfl_xor_sync(0xffffffffu, keep, 4);
        keep += __shfl_xor_sync(0xffffffffu, keep, 8);
        keep += __shfl_xor_sync(0xffffffffu, keep, 16);
        if (lane < 2) s_o[e0 + lane] = keep;
    }
    __syncthreads();

    // ---- LayerNorm: fused sum/sumsq packed reduce (one barrier round).
    float ov = 0.f;
    if (tid < EMB_) ov = s_o[tid] + b2[tid];

    if (warp < 4) {
        const float sv = ov, ssv = ov * ov;
        float keep = (lane & 1) ? ssv : sv;
        float send = (lane & 1) ? sv : ssv;
        keep += __shfl_xor_sync(0xffffffffu, send, 1);
        keep += __shfl_xor_sync(0xffffffffu, keep, 2);
        keep += __shfl_xor_sync(0xffffffffu, keep, 4);
        keep += __shfl_xor_sync(0xffffffffu, keep, 8);
        keep += __shfl_xor_sync(0xffffffffu, keep, 16);
        if (lane < 2) s_ln[warp][lane] = keep;   // [0]=sum, [1]=sumsq
    }
    __syncthreads();

    if (tid < EMB_) {
        const float Ssum  = s_ln[0][0] + s_ln[1][0] + s_ln[2][0] + s_ln[3][0];
        const float SSsum = s_ln[0][1] + s_ln[1][1] + s_ln[2][1] + s_ln[3][1];
        const float mu  = Ssum * (1.f / EMB_);
        const float var = SSsum * (1.f / EMB_) - mu * mu;
        const float y = (ov - mu) * rsqrtf(var + EPS_LN);
        out[(size_t)row * EMB_ + tid] = fmaf(y, gamma[tid], beta[tid]);
    }
}

extern "C" void kernel_launch(void* const* d_in, const int* in_sizes, int n_in,
                              void* d_out, int out_size)
{
    const float* rbf    = (const float*)d_in[0];
    const float* r_hat  = (const float*)d_in[1];
    const float* mask   = (const float*)d_in[2];
    const float* w_rad  = (const float*)d_in[3];
    const float* b_rad  = (const float*)d_in[4];
    const float* w1     = (const float*)d_in[5];
    const float* b1     = (const float*)d_in[6];
    const float* w2     = (const float*)d_in[7];
    const float* b2     = (const float*)d_in[8];
    const float* gamma  = (const float*)d_in[9];
    const float* beta   = (const float*)d_in[10];
    float* out = (float*)d_out;

    tba_fused<<<B_ * N_, 256>>>(rbf, r_hat, mask, w_rad, b_rad,
                                w1, b1, w2, b2, gamma, beta, out);
}

// round 17
// speedup vs baseline: 1.0278x; 1.0278x over previous
#include <cuda_runtime.h>

// ThreeBodyAggregation — moment-factorized, fully fused, 1 row per block.
// R12 champion structure; GEMV rewritten as two 8-load software-pipelined
// batches so the w2 loads take 2 L2 round trips instead of 8.
//
// agg_l(b,i) = sum_{j,k} w_j w_k P_l(u_j.u_k) computed exactly via weighted
// direction moments (Legendre monomial expansion). All agg terms are weighted
// sums of SQUARES of the 20 moments:
//   agg0 = S^2
//   agg1 = |V|^2
//   agg2 = 1.5*||M||_F^2 - 0.5*S^2
//   agg3 = 2.5*||T||^2   - 1.5*|V|^2
// Then h = silu(agg @ w1^T + b1), o = h @ w2^T + b2, LayerNorm(o).

#define B_   4
#define N_   160
#define R_   64
#define EMB_ 128
#define HID_ 128
#define EPS_LN 1e-5f

__global__ __launch_bounds__(256, 5)
void tba_fused(const float* __restrict__ rbf,     // (B,N,N,R)
               const float* __restrict__ r_hat,   // (B,N,N,3)
               const float* __restrict__ mask,    // (B,N,N)
               const float* __restrict__ w_rad,   // (1,R)
               const float* __restrict__ b_rad,   // (1,)
               const float* __restrict__ w1,      // (HID,4)
               const float* __restrict__ b1,      // (HID,)
               const float* __restrict__ w2,      // (EMB,HID)
               const float* __restrict__ b2,      // (EMB,)
               const float* __restrict__ gamma,   // (EMB,)
               const float* __restrict__ beta,    // (EMB,)
               float* __restrict__ out)           // (B,N,EMB)
{
    __shared__ float s_w[N_];
    __shared__ float s_mask[N_];
    __shared__ float s_rh[N_ * 3];
    __shared__ float s_red[8][20];
    __shared__ float s_val[20];
    __shared__ float s_agg[4];
    __shared__ float s_h[HID_];
    __shared__ float s_o[EMB_];
    __shared__ float s_ln[4][2];

    const int tid  = threadIdx.x;
    const int lane = tid & 31;
    const int warp = tid >> 5;
    const int row  = blockIdx.x;
    const float brad = b_rad[0];

    // ---- mask + r_hat rows (coalesced float4; needed in Phase B).
    if (tid < 40)
        reinterpret_cast<float4*>(s_mask)[tid] =
            reinterpret_cast<const float4*>(mask + (size_t)row * N_)[tid];
    if (tid < 120)
        reinterpret_cast<float4*>(s_rh)[tid] =
            reinterpret_cast<const float4*>(r_hat + (size_t)row * (N_ * 3))[tid];

    // 8 lanes per j-row; lane c owns w_rad float4s c and c+8.
    const int c = lane & 7;
    const float4* wr4 = reinterpret_cast<const float4*>(w_rad);
    const float4 wr0 = wr4[c];
    const float4 wr1 = wr4[c + 8];

    const float4* rbf4 =
        reinterpret_cast<const float4*>(rbf + (size_t)row * (N_ * R_));

    // ---- Phase A: warp w covers j = 20w..20w+19; 4 j-rows per pass
    // (lane>>3 picks the row), 5 passes in two half-batches (3 + 2 passes,
    // max 6 float4 live -> 48-reg fit).
    const int jb = warp * 20 + (lane >> 3);
    {
        float4 a0[3], a1[3];
        #pragma unroll
        for (int p = 0; p < 3; ++p) {
            const size_t base = (size_t)(jb + 4 * p) * (R_ / 4);
            a0[p] = rbf4[base + c];
            a1[p] = rbf4[base + c + 8];
        }
        #pragma unroll
        for (int p = 0; p < 3; ++p) {
            float v = a0[p].x * wr0.x;
            v = fmaf(a0[p].y, wr0.y, v);
            v = fmaf(a0[p].z, wr0.z, v);
            v = fmaf(a0[p].w, wr0.w, v);
            v = fmaf(a1[p].x, wr1.x, v);
            v = fmaf(a1[p].y, wr1.y, v);
            v = fmaf(a1[p].z, wr1.z, v);
            v = fmaf(a1[p].w, wr1.w, v);
            v += __shfl_xor_sync(0xffffffffu, v, 1);
            v += __shfl_xor_sync(0xffffffffu, v, 2);
            v += __shfl_xor_sync(0xffffffffu, v, 4);
            if (c == 0)
                s_w[jb + 4 * p] = __frcp_rn(1.f + __expf(-(v + brad)));
        }
    }
    {
        float4 a0[2], a1[2];
        #pragma unroll
        for (int p = 0; p < 2; ++p) {
            const size_t base = (size_t)(jb + 4 * (p + 3)) * (R_ / 4);
            a0[p] = rbf4[base + c];
            a1[p] = rbf4[base + c + 8];
        }
        #pragma unroll
        for (int p = 0; p < 2; ++p) {
            float v = a0[p].x * wr0.x;
            v = fmaf(a0[p].y, wr0.y, v);
            v = fmaf(a0[p].z, wr0.z, v);
            v = fmaf(a0[p].w, wr0.w, v);
            v = fmaf(a1[p].x, wr1.x, v);
            v = fmaf(a1[p].y, wr1.y, v);
            v = fmaf(a1[p].z, wr1.z, v);
            v = fmaf(a1[p].w, wr1.w, v);
            v += __shfl_xor_sync(0xffffffffu, v, 1);
            v += __shfl_xor_sync(0xffffffffu, v, 2);
            v += __shfl_xor_sync(0xffffffffu, v, 4);
            if (c == 0)
                s_w[jb + 4 * (p + 3)] = __frcp_rn(1.f + __expf(-(v + brad)));
        }
    }
    __syncthreads();

    // ---- Phase B: weighted direction moments (20 accumulators).
    float acc[20];
    #pragma unroll
    for (int q = 0; q < 20; ++q) acc[q] = 0.f;
    if (tid < N_) {
        const float w = s_w[tid] * s_mask[tid];
        const float x = s_rh[3 * tid];
        const float y = s_rh[3 * tid + 1];
        const float z = s_rh[3 * tid + 2];
        const float wx = w * x, wy = w * y, wz = w * z;
        const float wxx = wx * x, wyy = wy * y, wzz = wz * z;
        const float wxy = wx * y, wxz = wx * z, wyz = wy * z;
        acc[0]  = w;
        acc[1]  = wx;  acc[2]  = wy;  acc[3]  = wz;
        acc[4]  = wxx; acc[5]  = wyy; acc[6]  = wzz;
        acc[7]  = wxy; acc[8]  = wxz; acc[9]  = wyz;
        acc[10] = wxx * x; acc[11] = wyy * y; acc[12] = wzz * z;
        acc[13] = wxx * y; acc[14] = wxx * z;
        acc[15] = wyy * x; acc[16] = wyy * z;
        acc[17] = wzz * x; acc[18] = wzz * y;
        acc[19] = wxy * z;
    }
    // Packed 4-group reduce: 6 shuffles per 4 moments (30 total).
    #pragma unroll
    for (int g = 0; g < 5; ++g) {
        const int b = 4 * g;
        float keepA = (lane & 1) ? acc[b + 1] : acc[b + 0];
        float sendA = (lane & 1) ? acc[b + 0] : acc[b + 1];
        keepA += __shfl_xor_sync(0xffffffffu, sendA, 1);
        float keepB = (lane & 1) ? acc[b + 3] : acc[b + 2];
        float sendB = (lane & 1) ? acc[b + 2] : acc[b + 3];
        keepB += __shfl_xor_sync(0xffffffffu, sendB, 1);
        float keep = (lane & 2) ? keepB : keepA;
        float send = (lane & 2) ? keepA : keepB;
        keep += __shfl_xor_sync(0xffffffffu, send, 2);
        keep += __shfl_xor_sync(0xffffffffu, keep, 4);
        keep += __shfl_xor_sync(0xffffffffu, keep, 8);
        keep += __shfl_xor_sync(0xffffffffu, keep, 16);
        if (lane < 4) s_red[warp][b + lane] = keep;
    }
    __syncthreads();

    // ---- Combine: warp 0 lane q<20 sums 8 partials, squares with coef.
    if (warp == 0) {
        if (lane < 20) {
            float m = 0.f;
            #pragma unroll
            for (int u = 0; u < 8; ++u) m += s_red[u][lane];
            // coef: q0:1, q1-6:1, q7-9:2, q10-12:1, q13-18:3, q19:6
            float cf = 1.f;
            if (lane >= 7 && lane <= 9) cf = 2.f;
            else if (lane >= 13 && lane <= 18) cf = 3.f;
            else if (lane == 19) cf = 6.f;
            s_val[lane] = cf * m * m;
        }
        __syncwarp();
        if (lane == 0) {
            const float S2 = s_val[0];
            const float V2 = s_val[1] + s_val[2] + s_val[3];
            float Q2 = 0.f, Q3 = 0.f;
            #pragma unroll
            for (int q = 4; q < 10; ++q) Q2 += s_val[q];
            #pragma unroll
            for (int q = 10; q < 20; ++q) Q3 += s_val[q];
            s_agg[0] = S2;
            s_agg[1] = V2;
            s_agg[2] = 1.5f * Q2 - 0.5f * S2;
            s_agg[3] = 2.5f * Q3 - 1.5f * V2;
        }
    }
    __syncthreads();

    // ---- Phase C: h = silu(agg @ w1^T + b1). First 128 threads.
    if (tid < HID_) {
        const float4 wv1 = reinterpret_cast<const float4*>(w1)[tid];
        float hv = fmaf(s_agg[0], wv1.x,
                   fmaf(s_agg[1], wv1.y,
                   fmaf(s_agg[2], wv1.z,
                   fmaf(s_agg[3], wv1.w, b1[tid]))));
        hv = hv * __frcp_rn(1.f + __expf(-hv));
        s_h[tid] = hv;
    }
    __syncthreads();

    // Per-lane h slice in registers.
    const float4 hv = reinterpret_cast<const float4*>(s_h)[lane];

    // ---- GEMV, software-pipelined in two 8-load batches.
    // Warp w handles outputs e = 16w..16w+15, paired (even lanes carry
    // e0 partials, odd e1): 5 shuffles per 2 outputs. Batch-2 loads issue
    // before batch-1's shuffle chains so their latency overlaps.
    const float4* w2v = reinterpret_cast<const float4*>(w2) + warp * 512 + lane;
    float part1[4], part2[4];

    {   // Batch 1: outputs 16w+0 .. 16w+7 (8 coalesced LDG.128 together).
        float4 wa[4], wb[4];
        #pragma unroll
        for (int q = 0; q < 4; ++q) {
            wa[q] = w2v[(2 * q) * 32];
            wb[q] = w2v[(2 * q + 1) * 32];
        }
        #pragma unroll
        for (int q = 0; q < 4; ++q) {
            float a0 = fmaf(wa[q].x, hv.x, fmaf(wa[q].y, hv.y,
                       fmaf(wa[q].z, hv.z, wa[q].w * hv.w)));
            float a1 = fmaf(wb[q].x, hv.x, fmaf(wb[q].y, hv.y,
                       fmaf(wb[q].z, hv.z, wb[q].w * hv.w)));
            float keep = (lane & 1) ? a1 : a0;
            float send = (lane & 1) ? a0 : a1;
            part1[q] = keep + __shfl_xor_sync(0xffffffffu, send, 1);
        }
    }
    {   // Batch 2 loads: issue now, consume after batch-1's shuffle chains.
        float4 wa[4], wb[4];
        #pragma unroll
        for (int q = 0; q < 4; ++q) {
            wa[q] = w2v[(8 + 2 * q) * 32];
            wb[q] = w2v[(8 + 2 * q + 1) * 32];
        }
        // Batch 1: finish 4 independent (pipelined) shuffle chains.
        #pragma unroll
        for (int q = 0; q < 4; ++q) {
            float k = part1[q];
            k += __shfl_xor_sync(0xffffffffu, k, 2);
            k += __shfl_xor_sync(0xffffffffu, k, 4);
            k += __shfl_xor_sync(0xffffffffu, k, 8);
            k += __shfl_xor_sync(0xffffffffu, k, 16);
            if (lane < 2) s_o[warp * 16 + 2 * q + lane] = k;
        }
        // Batch 2: FMAs + reductions.
        #pragma unroll
        for (int q = 0; q < 4; ++q) {
            float a0 = fmaf(wa[q].x, hv.x, fmaf(wa[q].y, hv.y,
                       fmaf(wa[q].z, hv.z, wa[q].w * hv.w)));
            float a1 = fmaf(wb[q].x, hv.x, fmaf(wb[q].y, hv.y,
                       fmaf(wb[q].z, hv.z, wb[q].w * hv.w)));
            float keep = (lane & 1) ? a1 : a0;
            float send = (lane & 1) ? a0 : a1;
            part2[q] = keep + __shfl_xor_sync(0xffffffffu, send, 1);
        }
        #pragma unroll
        for (int q = 0; q < 4; ++q) {
            float k = part2[q];
            k += __shfl_xor_sync(0xffffffffu, k, 2);
            k += __shfl_xor_sync(0xffffffffu, k, 4);
            k += __shfl_xor_sync(0xffffffffu, k, 8);
            k += __shfl_xor_sync(0xffffffffu, k, 16);
            if (lane < 2) s_o[warp * 16 + 8 + 2 * q + lane] = k;
        }
    }
    __syncthreads();

    // ---- LayerNorm: fused sum/sumsq packed reduce (one barrier round).
    float ov = 0.f;
    if (tid < EMB_) ov = s_o[tid] + b2[tid];

    if (warp < 4) {
        const float sv = ov, ssv = ov * ov;
        float keep = (lane & 1) ? ssv : sv;
        float send = (lane & 1) ? sv : ssv;
        keep += __shfl_xor_sync(0xffffffffu, send, 1);
        keep += __shfl_xor_sync(0xffffffffu, keep, 2);
        keep += __shfl_xor_sync(0xffffffffu, keep, 4);
        keep += __shfl_xor_sync(0xffffffffu, keep, 8);
        keep += __shfl_xor_sync(0xffffffffu, keep, 16);
        if (lane < 2) s_ln[warp][lane] = keep;   // [0]=sum, [1]=sumsq
    }
    __syncthreads();

    if (tid < EMB_) {
        const float Ssum  = s_ln[0][0] + s_ln[1][0] + s_ln[2][0] + s_ln[3][0];
        const float SSsum = s_ln[0][1] + s_ln[1][1] + s_ln[2][1] + s_ln[3][1];
        const float mu  = Ssum * (1.f / EMB_);
        const float var = SSsum * (1.f / EMB_) - mu * mu;
        const float y = (ov - mu) * rsqrtf(var + EPS_LN);
        out[(size_t)row * EMB_ + tid] = fmaf(y, gamma[tid], beta[tid]);
    }
}

extern "C" void kernel_launch(void* const* d_in, const int* in_sizes, int n_in,
                              void* d_out, int out_size)
{
    const float* rbf    = (const float*)d_in[0];
    const float* r_hat  = (const float*)d_in[1];
    const float* mask   = (const float*)d_in[2];
    const float* w_rad  = (const float*)d_in[3];
    const float* b_rad  = (const float*)d_in[4];
    const float* w1     = (const float*)d_in[5];
    const float* b1     = (const float*)d_in[6];
    const float* w2     = (const float*)d_in[7];
    const float* b2     = (const float*)d_in[8];
    const float* gamma  = (const float*)d_in[9];
    const float* beta   = (const float*)d_in[10];
    float* out = (float*)d_out;

    tba_fused<<<B_ * N_, 256>>>(rbf, r_hat, mask, w_rad, b_rad,
                                w1, b1, w2, b2, gamma, beta, out);
}